// round 11
// baseline (speedup 1.0000x reference)
#include <cuda_runtime.h>
#include <cuda_fp16.h>
#include <math.h>

#define DIN  128
#define DH   128
#define DOUT 16
#define NCAP 100352
#define ECAP 1600128

// ---- scratch (static __device__ per harness rules) ----
__device__ int   g_is64;            // 1 if edge_index is int64, 0 if int32
__device__ int   g_deg[NCAP];
__device__ float g_dinv[NCAP];
__device__ int   g_incl[NCAP];
__device__ int   g_bsums[256];
__device__ int   g_rowptr[NCAP + 1];
__device__ int   g_cursor[NCAP];
__device__ int   g_col[ECAP];
__device__ __align__(16) __half g_h1h[(size_t)NCAP * DH];  // (x@W1)*dinv[row], fp16
__device__ __align__(16) float  g_h2[(size_t)NCAP * DOUT]; // (a1@W2)*dinv[row]

union H4 { __half2 h2[2]; uint2 u; };   // 8B  (gather granule per lane)
union H8 { __half2 h2[4]; uint4 u; };   // 16B (store granule per thread)

// ------------------------------------------------------------------
// init: zero degree array; block 0 also detects edge_index dtype
// (int64 => high word of every entry is 0 since indices < 100K).
__global__ void k_init(const int* __restrict__ ei32, int e, int n) {
    int i = blockIdx.x * blockDim.x + threadIdx.x;
    if (i < n) g_deg[i] = 0;
    if (blockIdx.x == 0) {
        __shared__ int nz;
        if (threadIdx.x == 0) nz = 0;
        __syncthreads();
        int lim = (e < 4096) ? e : 4096;
        for (int t = threadIdx.x; t < lim; t += blockDim.x)
            if (ei32[2 * t + 1] != 0) nz = 1;   // benign race
        __syncthreads();
        if (threadIdx.x == 0) g_is64 = (nz == 0) ? 1 : 0;
    }
}

__device__ __forceinline__ int edge_at(const void* ei, size_t pos) {
    if (g_is64) return (int)((const long long*)ei)[pos];
    return ((const int*)ei)[pos];
}

__global__ void k_degree(const void* __restrict__ ei, int e, int n) {
    int i = blockIdx.x * blockDim.x + threadIdx.x;
    if (i < e) {
        int d = edge_at(ei, (size_t)e + i);
        if ((unsigned)d < (unsigned)n) atomicAdd(&g_deg[d], 1);
    }
}

// block-level inclusive scan (1024 elems / block) + dinv computation
__global__ void k_scan1(int n) {
    __shared__ int s[1024];
    int i = blockIdx.x * 1024 + threadIdx.x;
    int d = (i < n) ? g_deg[i] : 0;
    s[threadIdx.x] = d;
    if (i < n) g_dinv[i] = rsqrtf((float)(d + 1)); // +1 self loop
    __syncthreads();
    for (int off = 1; off < 1024; off <<= 1) {
        int t = (threadIdx.x >= off) ? s[threadIdx.x - off] : 0;
        __syncthreads();
        s[threadIdx.x] += t;
        __syncthreads();
    }
    if (i < n) g_incl[i] = s[threadIdx.x];
    if (threadIdx.x == 1023) g_bsums[blockIdx.x] = s[1023];
}

// scan3 with the (<=128-entry) block-sum scan folded in: every block
// redundantly scans g_bsums in smem (cheap), then computes rowptr/cursor.
__global__ void k_scan3(int n, int nb) {
    __shared__ int sb[128];
    int tid = threadIdx.x;
    if (tid < 128) sb[tid] = (tid < nb) ? g_bsums[tid] : 0;
    __syncthreads();
    for (int off = 1; off < 128; off <<= 1) {
        int t = (tid < 128 && tid >= off) ? sb[tid - off] : 0;
        __syncthreads();
        if (tid < 128) sb[tid] += t;
        __syncthreads();
    }
    int i = blockIdx.x * blockDim.x + tid;
    if (i < n) {
        int blk = i >> 10;
        int boff = blk ? sb[blk - 1] : 0;
        int v = g_incl[i] - g_deg[i] + boff;   // exclusive
        g_rowptr[i] = v;
        g_cursor[i] = v;
    }
    if (blockIdx.x == 0 && tid == 0) g_rowptr[n] = sb[127];
}

// ------------------------------------------------------------------
// FMA4: acc += scal * vec  (parameter names must NOT collide with x/y/z/w)
#define FMA4(acc, vec, scal) do { \
    (acc).x = fmaf((scal), (vec).x, (acc).x); \
    (acc).y = fmaf((scal), (vec).y, (acc).y); \
    (acc).z = fmaf((scal), (vec).z, (acc).z); \
    (acc).w = fmaf((scal), (vec).w, (acc).w); } while (0)

#define KC 32          // k-chunk size for GEMM1
#define GF_BLOCKS 256  // CSR-fill blocks placed FIRST in the fused grid

// Fused: blocks [0, GF_BLOCKS) do the CSR fill; blocks [GF_BLOCKS, ...)
// do GEMM1: h1h = fp16((x @ W1) * dinv[row]).
__global__ void __launch_bounds__(256, 1) k_fill_gemm1(const float* __restrict__ x,
                                                       const float* __restrict__ W1,
                                                       const void* __restrict__ ei,
                                                       int e, int n) {
    __shared__ float Ws[KC * DH];    // 16KB
    __shared__ float Xs[128 * KC];   // 16KB

    if (blockIdx.x < GF_BLOCKS) {
        int i0 = blockIdx.x * blockDim.x + threadIdx.x;
        int stride = GF_BLOCKS * blockDim.x;
        for (int i = i0; i < e; i += stride) {
            int s = edge_at(ei, (size_t)i);
            int d = edge_at(ei, (size_t)e + i);
            if ((unsigned)s < (unsigned)n && (unsigned)d < (unsigned)n) {
                int p = atomicAdd(&g_cursor[d], 1);
                if ((unsigned)p < (unsigned)ECAP) g_col[p] = s;
            }
        }
        return;
    }

    int row0 = (blockIdx.x - GF_BLOCKS) * 128;
    int tx = threadIdx.x & 15;
    int ty = threadIdx.x >> 4;
    float4 a0[8], a1[8];
    #pragma unroll
    for (int r = 0; r < 8; r++) { a0[r] = make_float4(0,0,0,0); a1[r] = make_float4(0,0,0,0); }

    const float4* W4 = (const float4*)W1;
    const float4* x4 = (const float4*)x;
    float4* Ws4 = (float4*)Ws;
    float4* Xs4 = (float4*)Xs;

    for (int kc = 0; kc < DIN / KC; kc++) {
        for (int i = threadIdx.x; i < KC * DH / 4; i += 256)
            Ws4[i] = W4[kc * (KC * DH / 4) + i];
        for (int i = threadIdx.x; i < 128 * KC / 4; i += 256) {
            int r = i >> 3, c = i & 7, gr = row0 + r;
            Xs4[i] = (gr < n) ? x4[(size_t)gr * 32 + kc * 8 + c]
                              : make_float4(0.f, 0.f, 0.f, 0.f);
        }
        __syncthreads();

        const float* wp = Ws + tx * 8;
        #pragma unroll
        for (int k = 0; k < KC; k++) {
            float4 wv0 = *(const float4*)(wp + k * 128);
            float4 wv1 = *(const float4*)(wp + k * 128 + 4);
            #pragma unroll
            for (int r = 0; r < 8; r++) {
                float xv = Xs[(ty * 8 + r) * KC + k];
                FMA4(a0[r], wv0, xv);
                FMA4(a1[r], wv1, xv);
            }
        }
        __syncthreads();
    }

    #pragma unroll
    for (int r = 0; r < 8; r++) {
        int row = row0 + ty * 8 + r;
        if (row < n) {
            float dv = g_dinv[row];
            float4 o0 = a0[r], o1 = a1[r];
            o0.x *= dv; o0.y *= dv; o0.z *= dv; o0.w *= dv;
            o1.x *= dv; o1.y *= dv; o1.z *= dv; o1.w *= dv;
            H8 st;
            st.h2[0] = __floats2half2_rn(o0.x, o0.y);
            st.h2[1] = __floats2half2_rn(o0.z, o0.w);
            st.h2[2] = __floats2half2_rn(o1.x, o1.y);
            st.h2[3] = __floats2half2_rn(o1.z, o1.w);
            *(uint4*)(g_h1h + (size_t)row * DH + tx * 8) = st.u;
        }
    }
}

// ------------------------------------------------------------------
// Fused Agg1 + GEMM2: warp per node, fp16 gather, x8 unroll.
// lane owns features lane*4..lane*4+3 (matches GEMM2 k-ownership).
__device__ __forceinline__ void acc_h4(float4& acc, uint2 raw) {
    H4 t; t.u = raw;
    float2 f0 = __half22float2(t.h2[0]);
    float2 f1 = __half22float2(t.h2[1]);
    acc.x += f0.x; acc.y += f0.y; acc.z += f1.x; acc.w += f1.y;
}

__global__ void __launch_bounds__(256) k_agg1_gemm2(const float* __restrict__ b1,
                                                    const float* __restrict__ W2, int n) {
    __shared__ float W2s[DH * DOUT]; // 8KB
    for (int i = threadIdx.x; i < DH * DOUT; i += blockDim.x) W2s[i] = W2[i];
    __syncthreads();

    int warp = (blockIdx.x * blockDim.x + threadIdx.x) >> 5;
    int lane = threadIdx.x & 31;
    if (warp >= n) return;

    int beg = g_rowptr[warp], end = g_rowptr[warp + 1];
    const uint2* h8 = (const uint2*)g_h1h;     // 8B granules; row = 32 granules
    float4 acc = make_float4(0.f, 0.f, 0.f, 0.f);
    acc_h4(acc, h8[(size_t)warp * 32 + lane]); // self (already *dinv[i])

    int e = beg;
    for (; e + 7 < end; e += 8) {
        int j0 = g_col[e],     j1 = g_col[e + 1], j2 = g_col[e + 2], j3 = g_col[e + 3];
        int j4 = g_col[e + 4], j5 = g_col[e + 5], j6 = g_col[e + 6], j7 = g_col[e + 7];
        uint2 v0 = h8[(size_t)j0 * 32 + lane];
        uint2 v1 = h8[(size_t)j1 * 32 + lane];
        uint2 v2 = h8[(size_t)j2 * 32 + lane];
        uint2 v3 = h8[(size_t)j3 * 32 + lane];
        uint2 v4 = h8[(size_t)j4 * 32 + lane];
        uint2 v5 = h8[(size_t)j5 * 32 + lane];
        uint2 v6 = h8[(size_t)j6 * 32 + lane];
        uint2 v7 = h8[(size_t)j7 * 32 + lane];
        acc_h4(acc, v0); acc_h4(acc, v1); acc_h4(acc, v2); acc_h4(acc, v3);
        acc_h4(acc, v4); acc_h4(acc, v5); acc_h4(acc, v6); acc_h4(acc, v7);
    }
    for (; e < end; e++) {
        int j = g_col[e];
        acc_h4(acc, h8[(size_t)j * 32 + lane]);
    }

    float di = g_dinv[warp];
    float4 b = ((const float4*)b1)[lane];
    float xs[4];
    xs[0] = fmaxf(fmaf(acc.x, di, b.x), 0.f);
    xs[1] = fmaxf(fmaf(acc.y, di, b.y), 0.f);
    xs[2] = fmaxf(fmaf(acc.z, di, b.z), 0.f);
    xs[3] = fmaxf(fmaf(acc.w, di, b.w), 0.f);

    // gemm2: register-resident a1 row; lane l owns k=4l..4l+3
    float4 c0 = make_float4(0,0,0,0), c1 = c0, c2 = c0, c3 = c0;
    int k0 = lane * 4;
    #pragma unroll
    for (int kk = 0; kk < 4; kk++) {
        const float4* wrow = (const float4*)(W2s + (k0 + kk) * DOUT);
        float s = xs[kk];
        float4 q0 = wrow[0], q1 = wrow[1], q2 = wrow[2], q3 = wrow[3];
        FMA4(c0, q0, s);
        FMA4(c1, q1, s);
        FMA4(c2, q2, s);
        FMA4(c3, q3, s);
    }
    float v[16] = {c0.x,c0.y,c0.z,c0.w, c1.x,c1.y,c1.z,c1.w,
                   c2.x,c2.y,c2.z,c2.w, c3.x,c3.y,c3.z,c3.w};
    #pragma unroll
    for (int off = 16; off >= 1; off >>= 1) {
        #pragma unroll
        for (int o = 0; o < 16; o++)
            v[o] += __shfl_xor_sync(0xffffffffu, v[o], off);
    }
    if (lane < 16)
        g_h2[(size_t)warp * DOUT + lane] = v[lane] * di;
}

// ------------------------------------------------------------------
// Agg2 + bias + log_softmax. Warp per node; two half-warps split edges,
// each unrolled x4.
__global__ void k_agg2(const float* __restrict__ b2, float* __restrict__ out, int n) {
    int warp = (blockIdx.x * blockDim.x + threadIdx.x) >> 5;
    int lane = threadIdx.x & 31;
    if (warp >= n) return;
    int c = lane & 15, half = lane >> 4;
    int beg = g_rowptr[warp], end = g_rowptr[warp + 1];
    float acc = (half == 0) ? g_h2[(size_t)warp * DOUT + c] : 0.f; // self
    int e = beg + half;
    for (; e + 6 < end; e += 8) {
        int j0 = g_col[e], j1 = g_col[e + 2], j2 = g_col[e + 4], j3 = g_col[e + 6];
        float u0 = g_h2[(size_t)j0 * DOUT + c];
        float u1 = g_h2[(size_t)j1 * DOUT + c];
        float u2 = g_h2[(size_t)j2 * DOUT + c];
        float u3 = g_h2[(size_t)j3 * DOUT + c];
        acc += (u0 + u1) + (u2 + u3);
    }
    for (; e < end; e += 2) {
        int j = g_col[e];
        acc += g_h2[(size_t)j * DOUT + c];
    }
    acc += __shfl_xor_sync(0xffffffffu, acc, 16);
    float di = g_dinv[warp];
    float logit = fmaf(acc, di, b2[c]);
    float m = logit;
    #pragma unroll
    for (int off = 8; off >= 1; off >>= 1)
        m = fmaxf(m, __shfl_xor_sync(0xffffffffu, m, off));
    float ex = expf(logit - m);
    float s = ex;
    #pragma unroll
    for (int off = 8; off >= 1; off >>= 1)
        s += __shfl_xor_sync(0xffffffffu, s, off);
    if (half == 0)
        out[(size_t)warp * DOUT + c] = logit - m - logf(s);
}

// ------------------------------------------------------------------
extern "C" void kernel_launch(void* const* d_in, const int* in_sizes, int n_in,
                              void* d_out, int out_size) {
    const float* x  = (const float*)d_in[0];
    const void*  ei = d_in[1];                 // int32 or int64, detected on device
    const float* W1 = (const float*)d_in[2];
    const float* b1 = (const float*)d_in[3];
    const float* W2 = (const float*)d_in[4];
    const float* b2 = (const float*)d_in[5];
    float* out = (float*)d_out;

    int n = in_sizes[0] / DIN;  // 100000
    int e = in_sizes[1] / 2;    // 1600000

    // graph build
    k_init  <<<(n + 255) / 256, 256>>>((const int*)ei, e, n);
    k_degree<<<(e + 255) / 256, 256>>>(ei, e, n);
    int nb = (n + 1023) / 1024;
    k_scan1 <<<nb, 1024>>>(n);
    k_scan3 <<<(n + 255) / 256, 256>>>(n, nb);

    // fused CSR-fill (first GF_BLOCKS) + GEMM1 (rest, fp16 epilogue)
    int g1 = (n + 127) / 128;
    k_fill_gemm1<<<GF_BLOCKS + g1, 256>>>(x, W1, ei, e, n);

    // fused layer-1 aggregation (fp16 gather) + layer-2 GEMM
    k_agg1_gemm2<<<(n + 7) / 8, 256>>>(b1, W2, n);

    // layer-2 aggregation + log_softmax
    k_agg2<<<(n + 7) / 8, 256>>>(b2, out, n);
}